// round 12
// baseline (speedup 1.0000x reference)
#include <cuda_runtime.h>
#include <cstdint>

// Problem constants
#define LL 2
#define BB 16
#define TT 512
#define HH 12
#define NL 4096   // (1+1)^12 leaves
#define NC 1000
#define NCHUNK 32 // token chunks per batch
#define TOKC 16   // tokens per chunk
#define NCTA 512

// GEMM tiling: 512 CTAs = 64 row-chunks x 8 col-tiles
#define G_LCH 64
#define G_CT  125

// Scratch + sync counters
__device__ float g_part[NCHUNK * BB * NL];  // [chunk][batch][leaf] (8 MB)
__device__ float g_avg[BB * NL];            // [batch][leaf] (256 KB)
__device__ int gA = 0;   // leaf-done
__device__ int gC = 0;   // reduce-done
__device__ int gB = 0;   // exit ticket (counter reset)

// ---- f32x2 helpers ---------------------------------------------------------
__device__ __forceinline__ unsigned long long pk2(float x, float y) {
    unsigned long long r;
    asm("mov.b64 %0, {%1, %2};" : "=l"(r) : "f"(x), "f"(y));
    return r;
}
__device__ __forceinline__ void fma2(unsigned long long& d,
                                     unsigned long long a,
                                     unsigned long long b) {
    asm("fma.rn.f32x2 %0, %1, %2, %0;" : "+l"(d) : "l"(a), "l"(b));
}
__device__ __forceinline__ void upk2(unsigned long long v, float& lo, float& hi) {
    asm("mov.b64 {%0, %1}, %2;" : "=f"(lo), "=f"(hi) : "l"(v));
}
__device__ __forceinline__ int ld_acquire(const int* p) {
    int v;
    asm volatile("ld.acquire.gpu.b32 %0, [%1];" : "=r"(v) : "l"(p));
    return v;
}

// ---------------------------------------------------------------------------
// Fused persistent kernel: 512 CTAs x 256 threads, 4 CTAs/SM co-resident
// (static smem ~9.3 KB, launch_bounds caps regs at 64).
// P0: leaf products for (b=blk>>5, chunk=blk&31) -> g_part; zero `out`.
// B1: grid spin barrier.
// P1: cooperative reduce g_part -> g_avg (128 entries per CTA).
// B2: grid spin barrier.
// P2: GEMM tile (rc=blk>>3 rows, ct=blk&7 cols): thread = 1 col x 8 batches,
//     8-deep double-buffered scalar LDG stream, split-K float atomics.
// ---------------------------------------------------------------------------
__global__ void __launch_bounds__(256, 4) fused_kernel(
    const float* __restrict__ x, const float* __restrict__ cuts,
    const float* __restrict__ score, float* __restrict__ out)
{
    __shared__ float P[TOKC * 128];   // 8 KB; reused as sA[64*16] (4 KB) in P2
    __shared__ float sx[TOKC * 12];
    __shared__ float sc[12];

    const int tid = threadIdx.x;
    const int blk = blockIdx.x;

    // Zero out (512*256 = 131072 >= 16000)
    const int gid = blk * 256 + tid;
    if (gid < BB * NC) out[gid] = 0.f;

    // ---- P0: leaf products ----
    {
        const int b     = blk >> 5;
        const int chunk = blk & 31;

        if (tid < 12) sc[tid] = cuts[tid];
        const float* xl = x + (size_t)(LL - 1) * BB * TT * HH
                            + ((size_t)b * TT + (size_t)chunk * TOKC) * HH;
        for (int i = tid; i < TOKC * 12; i += 256) sx[i] = xl[i];
        __syncthreads();

        // Phase A: 256 tasks (tok, half, g), 8 contiguous products each
        {
            const int tok  = tid >> 4;
            const int half = (tid >> 3) & 1;
            const int g    = tid & 7;
            const float* cr = sc + half * 6;
            const float c0f = cr[0], c1f = cr[1], c2f = cr[2];
            const float c3f = cr[3], c4f = cr[4], c5f = cr[5];
            const float* xr = sx + tok * 12 + half * 6;
            const float x0 = xr[0], x1 = xr[1], x2 = xr[2];
            const float x3 = xr[3], x4 = xr[4], x5 = xr[5];
            const float F0 = (g & 4) ? fmaf(2.f, x0, -c0f) : x0;
            const float F1 = (g & 2) ? fmaf(2.f, x1, -c1f) : x1;
            const float F2 = (g & 1) ? fmaf(2.f, x2, -c2f) : x2;
            const float p  = F0 * F1 * F2;
            const float b3 = fmaf(2.f, x3, -c3f);
            const float a4 = x4, b4 = fmaf(2.f, x4, -c4f);
            const float a5 = x5, b5 = fmaf(2.f, x5, -c5f);
            const float m00 = a4 * a5, m01 = a4 * b5;
            const float m10 = b4 * a5, m11 = b4 * b5;
            const float q0 = p * x3, q1 = p * b3;
            float* dst = P + tok * 128 + half * 64 + g * 8;
            *(float4*)dst       = make_float4(q0 * m00, q0 * m01, q0 * m10, q0 * m11);
            *(float4*)(dst + 4) = make_float4(q1 * m00, q1 * m01, q1 * m10, q1 * m11);
        }
        __syncthreads();

        // Phase B: rank-1 accumulation over 16 tokens -> g_part
        {
            const int w = tid >> 5, lane = tid & 31;
            unsigned long long acc2[4][2];
#pragma unroll
            for (int p = 0; p < 4; p++) { acc2[p][0] = 0ull; acc2[p][1] = 0ull; }

#pragma unroll 4
            for (int tok = 0; tok < TOKC; tok++) {
                const float* Pr = P + tok * 128;
                const ulonglong2* ph = (const ulonglong2*)(Pr + 8 * w);
                const ulonglong2 h0 = ph[0];
                const ulonglong2 h1 = ph[1];
                const float plo0 = Pr[64 + lane];
                const float plo1 = Pr[64 + lane + 32];
                const unsigned long long pl0 = pk2(plo0, plo0);
                const unsigned long long pl1 = pk2(plo1, plo1);
                fma2(acc2[0][0], h0.x, pl0); fma2(acc2[0][1], h0.x, pl1);
                fma2(acc2[1][0], h0.y, pl0); fma2(acc2[1][1], h0.y, pl1);
                fma2(acc2[2][0], h1.x, pl0); fma2(acc2[2][1], h1.x, pl1);
                fma2(acc2[3][0], h1.y, pl0); fma2(acc2[3][1], h1.y, pl1);
            }

            const float s = 1.f / (float)TT;
            float* dst = g_part + ((size_t)(chunk * BB + b)) * NL;
#pragma unroll
            for (int p = 0; p < 4; p++) {
                float u0v0, u1v0, u0v1, u1v1;
                upk2(acc2[p][0], u0v0, u1v0);
                upk2(acc2[p][1], u0v1, u1v1);
                const int u0 = 8 * w + 2 * p;
                dst[u0 * 64 + lane]            = u0v0 * s;
                dst[u0 * 64 + lane + 32]       = u0v1 * s;
                dst[(u0 + 1) * 64 + lane]      = u1v0 * s;
                dst[(u0 + 1) * 64 + lane + 32] = u1v1 * s;
            }
        }
    }

    // ---- B1: grid barrier (all 512 CTAs co-resident) ----
    __threadfence();
    __syncthreads();
    if (tid == 0) {
        atomicAdd(&gA, 1);
        while (ld_acquire(&gA) < NCTA) { __nanosleep(64); }
    }
    __syncthreads();

    // ---- P1: reduce 32 chunk partials -> g_avg (128 entries per CTA) ----
    if (tid < 128) {
        const int i = blk * 128 + tid;   // flat [b][l]
        float v = 0.f;
#pragma unroll
        for (int ch = 0; ch < NCHUNK; ch++)
            v += g_part[(size_t)ch * (BB * NL) + i];
        g_avg[i] = v;
    }

    // ---- B2: grid barrier ----
    __threadfence();
    __syncthreads();
    if (tid == 0) {
        atomicAdd(&gC, 1);
        while (ld_acquire(&gC) < NCTA) { __nanosleep(64); }
    }
    __syncthreads();

    // ---- P2: GEMM ----
    {
        float* sA = P;                    // reuse: [l][b], 64*16 floats
        const int l0 = (blk >> 3) * G_LCH;
        const int c0 = (blk & 7) * G_CT;

        // Build sA from g_avg: 256 tasks = 16 batches x 16 leaf-quads
        {
            const int bb = tid >> 4;
            const int lq = tid & 15;
            const float4 v = *(const float4*)(g_avg + (size_t)bb * NL + l0 + lq * 4);
            sA[(lq * 4 + 0) * 16 + bb] = v.x;
            sA[(lq * 4 + 1) * 16 + bb] = v.y;
            sA[(lq * 4 + 2) * 16 + bb] = v.z;
            sA[(lq * 4 + 3) * 16 + bb] = v.w;
        }
        __syncthreads();

        const int ci    = tid & 127;
        const int bhalf = tid >> 7;
        const int valid = (ci < G_CT);
        const int c     = c0 + ci;
        const int cs    = valid ? c : c0;            // safe in-range column
        const float* sp = score + (size_t)l0 * NC + cs;

        unsigned long long acc[4];
#pragma unroll
        for (int p = 0; p < 4; p++) acc[p] = 0ull;

        // 8-deep double-buffered scalar LDG stream, no barriers in the loop
        float scur[8], snxt[8];
#pragma unroll
        for (int i = 0; i < 8; i++) scur[i] = sp[(size_t)i * NC];

#pragma unroll
        for (int r = 0; r < G_LCH; r += 8) {
            if (r + 8 < G_LCH) {
#pragma unroll
                for (int i = 0; i < 8; i++)
                    snxt[i] = sp[(size_t)(r + 8 + i) * NC];
            }
#pragma unroll
            for (int i = 0; i < 8; i++) {
                const int row = r + i;
                const unsigned long long ss = pk2(scur[i], scur[i]);
                const ulonglong2* ar =
                    (const ulonglong2*)(sA + row * 16 + bhalf * 8);
                const ulonglong2 q0 = ar[0];
                const ulonglong2 q1 = ar[1];
                fma2(acc[0], ss, q0.x); fma2(acc[1], ss, q0.y);
                fma2(acc[2], ss, q1.x); fma2(acc[3], ss, q1.y);
            }
#pragma unroll
            for (int i = 0; i < 8; i++) scur[i] = snxt[i];
        }

        if (valid) {
#pragma unroll
            for (int p = 0; p < 4; p++) {
                float blo, bhi;
                upk2(acc[p], blo, bhi);
                const int bb = bhalf * 8 + 2 * p;
                atomicAdd(out + bb * NC + c,       blo);
                atomicAdd(out + (bb + 1) * NC + c, bhi);
            }
        }
    }

    // ---- Reset counters for next graph replay ----
    __syncthreads();
    if (tid == 0) {
        const int t = atomicAdd(&gB, 1);
        if (t == NCTA - 1) {
            atomicExch(&gB, 0);
            atomicExch(&gA, 0);
            atomicExch(&gC, 0);
        }
    }
}

// ---------------------------------------------------------------------------
extern "C" void kernel_launch(void* const* d_in, const int* in_sizes, int n_in,
                              void* d_out, int out_size)
{
    const float* x     = (const float*)d_in[0];  // (2,16,512,12)
    const float* cuts  = (const float*)d_in[1];  // (12,1)
    const float* score = (const float*)d_in[2];  // (4096,1000)
    float* out = (float*)d_out;                  // (16,1000)

    fused_kernel<<<NCTA, 256>>>(x, cuts, score, out);
}